// round 1
// baseline (speedup 1.0000x reference)
#include <cuda_runtime.h>
#include <cuda_bf16.h>
#include <cstdint>

// Problem constants
#define E_DIM   1024
#define HEADS   16
#define HDIM    64
#define BATCH   4
#define SEQ     2048
#define ROWS    (BATCH*SEQ)        // 8192
#define NQUBITS 6

// ---------------- device scratch (no allocations allowed) ----------------
__device__ float g_Wq[E_DIM*E_DIM];
__device__ float g_Wk[E_DIM*E_DIM];
__device__ float g_bq[E_DIM];
__device__ float g_bk[E_DIM];
__device__ float g_Mq[HDIM*HDIM];
__device__ float g_Mk[HDIM*HDIM];
__device__ float g_Q[(size_t)ROWS*E_DIM];
__device__ float g_K[(size_t)ROWS*E_DIM];
__device__ float g_V[(size_t)ROWS*E_DIM];
__device__ float g_O[(size_t)ROWS*E_DIM];

// ============================================================================
// Kernel 1: build effective quantum operator.
//   quantum(x) = postW @ (R @ (preW @ x + preb)) + postb + x
//              = Meff @ x + ceff,  Meff = postW@R@preW + I
// Also folds bias: beff[h*64+i] = sum_j Meff[i][j]*b_in[h*64+j] + ceff[i]
// One block, 64 threads (thread t owns column t / row t as noted).
// ============================================================================
__global__ void build_eff_kernel(
    const float* __restrict__ theta, const float* __restrict__ phi,
    const float* __restrict__ preW,  const float* __restrict__ preb,
    const float* __restrict__ postW, const float* __restrict__ postb,
    const float* __restrict__ b_in,
    float* __restrict__ Meff, float* __restrict__ beff)
{
    __shared__ float R[HDIM][HDIM];
    __shared__ float T[HDIM][HDIM];
    __shared__ float rb[HDIM];
    __shared__ float ctb[NQUBITS], stb[NQUBITS], cpb[NQUBITS];

    const int t = threadIdx.x;   // 0..63
    if (t < NQUBITS) {
        ctb[t] = cosf(theta[t]);
        stb[t] = sinf(theta[t]);
        cpb[t] = cosf(phi[t]);
    }
    __syncthreads();

    // Column t of R = stages applied to e_t
    float v[HDIM];
    for (int i = 0; i < HDIM; i++) v[i] = (i == t) ? 1.f : 0.f;
    for (int q = 0; q < NQUBITS; q++) {
        const int mask = 1 << q;
        const float c = ctb[q], s = stb[q], p = cpb[q];
        for (int i0 = 0; i0 < HDIM; i0++) {
            if (i0 & mask) continue;
            const int i1 = i0 | mask;
            float x0 = v[i0], x1 = v[i1];
            v[i0] = c * x0 - s * x1;
            v[i1] = (s * x0 + c * x1) * p;
        }
    }
    for (int i = 0; i < HDIM; i++) R[i][t] = v[i];
    __syncthreads();

    // T = R @ preW  (column t)
    for (int i = 0; i < HDIM; i++) {
        float acc = 0.f;
        for (int k = 0; k < HDIM; k++) acc += R[i][k] * preW[k*HDIM + t];
        T[i][t] = acc;
    }
    __syncthreads();

    // Meff = postW @ T + I  (column t)
    for (int i = 0; i < HDIM; i++) {
        float acc = (i == t) ? 1.f : 0.f;
        for (int k = 0; k < HDIM; k++) acc += postW[i*HDIM + k] * T[k][t];
        Meff[i*HDIM + t] = acc;
    }

    // rb = R @ preb  (element t)
    {
        float acc = 0.f;
        for (int j = 0; j < HDIM; j++) acc += R[t][j] * preb[j];
        rb[t] = acc;
    }
    __syncthreads();

    // ceff[t] = postW[t,:] @ rb + postb[t]
    float ce = postb[t];
    for (int k = 0; k < HDIM; k++) ce += postW[t*HDIM + k] * rb[k];

    __syncthreads();  // Meff global writes visible within block

    // beff per head
    for (int h = 0; h < HEADS; h++) {
        float b = ce;
        for (int j = 0; j < HDIM; j++) b += Meff[t*HDIM + j] * b_in[h*HDIM + j];
        beff[h*HDIM + t] = b;
    }
}

// ============================================================================
// Kernel 2: fold Meff into projection weights.
//   Weff[h*64+i, e] = sum_j Meff[i][j] * W[h*64+j, e]
// grid (HEADS, E/256), block 256. Each thread owns one e-column, 64 accums.
// ============================================================================
__global__ __launch_bounds__(256) void fold_weights_kernel(
    const float* __restrict__ W, const float* __restrict__ Meff,
    float* __restrict__ Weff)
{
    __shared__ float Ms[HDIM*HDIM];
    const int h = blockIdx.x;
    const int e = blockIdx.y * 256 + threadIdx.x;
    for (int p = threadIdx.x; p < HDIM*HDIM; p += 256) Ms[p] = Meff[p];
    __syncthreads();

    float acc[HDIM];
    #pragma unroll
    for (int i = 0; i < HDIM; i++) acc[i] = 0.f;

    for (int j = 0; j < HDIM; j++) {
        const float w = W[(size_t)(h*HDIM + j) * E_DIM + e];
        #pragma unroll
        for (int i = 0; i < HDIM; i++) acc[i] += Ms[i*HDIM + j] * w;
    }
    for (int i = 0; i < HDIM; i++)
        Weff[(size_t)(h*HDIM + i) * E_DIM + e] = acc[i];
}

// ============================================================================
// Kernel 3: SGEMM with bias. C[m,n] = sum_k A[m,k]*W[n,k] + bias[n]
// A: ROWS x 1024, W: 1024 x 1024 (row-major, N x K), fixed N=K=1024.
// layout 0: C standard (m*1024+n)    -> final output projection
// layout 1: C head-major (b,h,s,d)   -> Q/K/V for attention
// 128x128x8 tiles, 8x8 per thread, 256 threads, double-buffered smem.
// ============================================================================
__global__ __launch_bounds__(256) void sgemm_bias_kernel(
    const float* __restrict__ A, const float* __restrict__ W,
    const float* __restrict__ bias, float* __restrict__ C, int layout)
{
    __shared__ float As[2][8][128];
    __shared__ float Bs[2][8][128];

    const int tid  = threadIdx.x;
    const int m0   = blockIdx.y * 128;
    const int n0   = blockIdx.x * 128;
    const int lr   = tid >> 1;           // 0..127
    const int lseg = (tid & 1) * 4;      // 0 or 4
    const int tr   = tid >> 4;           // 0..15
    const int tc   = tid & 15;           // 0..15

    const float* Aptr = A + (size_t)(m0 + lr) * E_DIM + lseg;
    const float* Wptr = W + (size_t)(n0 + lr) * E_DIM + lseg;

    // preload tile 0
    {
        float4 a = *(const float4*)Aptr;
        float4 b = *(const float4*)Wptr;
        As[0][lseg+0][lr] = a.x; As[0][lseg+1][lr] = a.y;
        As[0][lseg+2][lr] = a.z; As[0][lseg+3][lr] = a.w;
        Bs[0][lseg+0][lr] = b.x; Bs[0][lseg+1][lr] = b.y;
        Bs[0][lseg+2][lr] = b.z; Bs[0][lseg+3][lr] = b.w;
    }
    __syncthreads();

    float acc[8][8];
    #pragma unroll
    for (int i = 0; i < 8; i++)
        #pragma unroll
        for (int j = 0; j < 8; j++) acc[i][j] = 0.f;

    int buf = 0;
    for (int kt = 0; kt < E_DIM/8; kt++) {
        float4 an = make_float4(0,0,0,0), bn = make_float4(0,0,0,0);
        const bool more = (kt + 1 < E_DIM/8);
        if (more) {
            an = *(const float4*)(Aptr + (kt+1)*8);
            bn = *(const float4*)(Wptr + (kt+1)*8);
        }
        #pragma unroll
        for (int k = 0; k < 8; k++) {
            float4 a0 = *(const float4*)(&As[buf][k][tr*8]);
            float4 a1 = *(const float4*)(&As[buf][k][tr*8+4]);
            float4 b0 = *(const float4*)(&Bs[buf][k][tc*8]);
            float4 b1 = *(const float4*)(&Bs[buf][k][tc*8+4]);
            float av[8] = {a0.x,a0.y,a0.z,a0.w,a1.x,a1.y,a1.z,a1.w};
            float bv[8] = {b0.x,b0.y,b0.z,b0.w,b1.x,b1.y,b1.z,b1.w};
            #pragma unroll
            for (int i = 0; i < 8; i++)
                #pragma unroll
                for (int j = 0; j < 8; j++)
                    acc[i][j] += av[i] * bv[j];
        }
        if (more) {
            const int nb = buf ^ 1;
            As[nb][lseg+0][lr] = an.x; As[nb][lseg+1][lr] = an.y;
            As[nb][lseg+2][lr] = an.z; As[nb][lseg+3][lr] = an.w;
            Bs[nb][lseg+0][lr] = bn.x; Bs[nb][lseg+1][lr] = bn.y;
            Bs[nb][lseg+2][lr] = bn.z; Bs[nb][lseg+3][lr] = bn.w;
        }
        __syncthreads();
        buf ^= 1;
    }

    // epilogue
    const int ncol = n0 + tc*8;
    float4 bb0 = *(const float4*)(bias + ncol);
    float4 bb1 = *(const float4*)(bias + ncol + 4);
    const float bvv[8] = {bb0.x,bb0.y,bb0.z,bb0.w,bb1.x,bb1.y,bb1.z,bb1.w};

    #pragma unroll
    for (int i = 0; i < 8; i++) {
        const int m = m0 + tr*8 + i;
        float4 o0, o1;
        o0.x = acc[i][0]+bvv[0]; o0.y = acc[i][1]+bvv[1];
        o0.z = acc[i][2]+bvv[2]; o0.w = acc[i][3]+bvv[3];
        o1.x = acc[i][4]+bvv[4]; o1.y = acc[i][5]+bvv[5];
        o1.z = acc[i][6]+bvv[6]; o1.w = acc[i][7]+bvv[7];
        float* dst;
        if (layout == 0) {
            dst = C + (size_t)m * E_DIM + ncol;
        } else {
            const int b = m >> 11, s = m & 2047;
            const int h = ncol >> 6, d = ncol & 63;
            dst = C + ((size_t)(b*HEADS + h) * SEQ + s) * HDIM + d;
        }
        *(float4*)(dst)     = o0;
        *(float4*)(dst + 4) = o1;
    }
}

// ============================================================================
// Kernel 4: flash attention, fp32. Br=Bc=64, Dh=64, 256 threads.
// Q/K/V in (B,H,S,Dh) contiguous per (b,h). Output in (B,S,H,Dh)=(B,S,E).
// Thread (ty,tx): ty=tid>>4 (row group, 4 rows), tx=tid&15 (col group, 4 cols)
// ============================================================================
#define KV_STRIDE 68  // padded row stride (floats), keeps 16B alignment

__global__ void flash_attn_kernel(
    const float* __restrict__ Q, const float* __restrict__ K,
    const float* __restrict__ V, float* __restrict__ O)
{
    extern __shared__ float sm[];
    float* Qs = sm;                          // [64][64] transposed: Qs[k*64 + r]
    float* KV = sm + 64*64;                  // K: [d][n] stride 68 / V: [n][d] stride 68
    float* Ps = KV + 64*KV_STRIDE;           // [64][64]

    const int tid = threadIdx.x;
    const int tx = tid & 15, ty = tid >> 4;
    const int bh = blockIdx.y;               // b*16+h
    const int q0 = blockIdx.x * 64;

    const float* Qh = Q + (size_t)bh * SEQ * HDIM;
    const float* Kh = K + (size_t)bh * SEQ * HDIM;
    const float* Vh = V + (size_t)bh * SEQ * HDIM;

    // Load Q tile transposed, pre-scaled by 1/sqrt(Dh)=0.125
    for (int p = tid; p < 1024; p += 256) {
        const int r = p >> 4;
        const int d = (p & 15) << 2;
        float4 v = *(const float4*)(Qh + (size_t)(q0 + r) * HDIM + d);
        Qs[(d+0)*64 + r] = v.x * 0.125f;
        Qs[(d+1)*64 + r] = v.y * 0.125f;
        Qs[(d+2)*64 + r] = v.z * 0.125f;
        Qs[(d+3)*64 + r] = v.w * 0.125f;
    }

    float mrow[4], lrow[4], o[4][4];
    #pragma unroll
    for (int i = 0; i < 4; i++) {
        mrow[i] = -1e30f; lrow[i] = 0.f;
        #pragma unroll
        for (int j = 0; j < 4; j++) o[i][j] = 0.f;
    }

    for (int kt = 0; kt < SEQ/64; kt++) {
        const int n0 = kt * 64;
        __syncthreads();  // KV free to overwrite; Ps reads done; Qs ready (iter 0)

        // Load K tile transposed: KV[d*68 + n]
        for (int p = tid; p < 1024; p += 256) {
            const int r = p >> 4;
            const int d = (p & 15) << 2;
            float4 v = *(const float4*)(Kh + (size_t)(n0 + r) * HDIM + d);
            KV[(d+0)*KV_STRIDE + r] = v.x;
            KV[(d+1)*KV_STRIDE + r] = v.y;
            KV[(d+2)*KV_STRIDE + r] = v.z;
            KV[(d+3)*KV_STRIDE + r] = v.w;
        }
        __syncthreads();

        // S = Q @ K^T (scaled)
        float s[4][4];
        #pragma unroll
        for (int i = 0; i < 4; i++)
            #pragma unroll
            for (int j = 0; j < 4; j++) s[i][j] = 0.f;

        #pragma unroll 8
        for (int k = 0; k < 64; k++) {
            float4 qa = *(const float4*)(Qs + k*64 + ty*4);
            float4 kb = *(const float4*)(KV + k*KV_STRIDE + tx*4);
            const float qv[4] = {qa.x, qa.y, qa.z, qa.w};
            const float kv[4] = {kb.x, kb.y, kb.z, kb.w};
            #pragma unroll
            for (int i = 0; i < 4; i++)
                #pragma unroll
                for (int j = 0; j < 4; j++)
                    s[i][j] += qv[i] * kv[j];
        }
        __syncthreads();  // done reading K from KV

        // Load V tile: KV[n*68 + d]
        for (int p = tid; p < 1024; p += 256) {
            const int r = p >> 4;
            const int d = (p & 15) << 2;
            float4 v = *(const float4*)(Vh + (size_t)(n0 + r) * HDIM + d);
            *(float4*)(KV + r*KV_STRIDE + d) = v;
        }

        // Online softmax on register fragment (rows span 16 lanes: tx=lane&15)
        #pragma unroll
        for (int i = 0; i < 4; i++) {
            float mt = fmaxf(fmaxf(s[i][0], s[i][1]), fmaxf(s[i][2], s[i][3]));
            mt = fmaxf(mt, __shfl_xor_sync(0xffffffffu, mt, 1));
            mt = fmaxf(mt, __shfl_xor_sync(0xffffffffu, mt, 2));
            mt = fmaxf(mt, __shfl_xor_sync(0xffffffffu, mt, 4));
            mt = fmaxf(mt, __shfl_xor_sync(0xffffffffu, mt, 8));
            const float mn = fmaxf(mrow[i], mt);
            const float alpha = __expf(mrow[i] - mn);
            #pragma unroll
            for (int j = 0; j < 4; j++) s[i][j] = __expf(s[i][j] - mn);
            float rs = s[i][0] + s[i][1] + s[i][2] + s[i][3];
            rs += __shfl_xor_sync(0xffffffffu, rs, 1);
            rs += __shfl_xor_sync(0xffffffffu, rs, 2);
            rs += __shfl_xor_sync(0xffffffffu, rs, 4);
            rs += __shfl_xor_sync(0xffffffffu, rs, 8);
            lrow[i] = lrow[i] * alpha + rs;
            mrow[i] = mn;
            #pragma unroll
            for (int j = 0; j < 4; j++) o[i][j] *= alpha;
        }

        // Write P fragment to shared
        #pragma unroll
        for (int i = 0; i < 4; i++)
            *(float4*)(Ps + (ty*4 + i)*64 + tx*4) =
                make_float4(s[i][0], s[i][1], s[i][2], s[i][3]);
        __syncthreads();  // V loaded + P written

        // O += P @ V
        #pragma unroll 8
        for (int k = 0; k < 64; k++) {
            const float p0 = Ps[(ty*4+0)*64 + k];
            const float p1 = Ps[(ty*4+1)*64 + k];
            const float p2 = Ps[(ty*4+2)*64 + k];
            const float p3 = Ps[(ty*4+3)*64 + k];
            float4 vb = *(const float4*)(KV + k*KV_STRIDE + tx*4);
            const float vv[4] = {vb.x, vb.y, vb.z, vb.w};
            const float pv[4] = {p0, p1, p2, p3};
            #pragma unroll
            for (int i = 0; i < 4; i++)
                #pragma unroll
                for (int j = 0; j < 4; j++)
                    o[i][j] += pv[i] * vv[j];
        }
    }

    // Epilogue: normalize and store in (B,S,E) layout
    const int b = bh >> 4, h = bh & 15;
    #pragma unroll
    for (int i = 0; i < 4; i++) {
        const float inv = 1.f / lrow[i];
        float4 r = make_float4(o[i][0]*inv, o[i][1]*inv, o[i][2]*inv, o[i][3]*inv);
        const size_t idx = ((size_t)b*SEQ + q0 + ty*4 + i) * E_DIM + h*HDIM + tx*4;
        *(float4*)(O + idx) = r;
    }
}

// ============================================================================
// Host launcher
// ============================================================================
extern "C" void kernel_launch(void* const* d_in, const int* in_sizes, int n_in,
                              void* d_out, int out_size)
{
    (void)in_sizes; (void)n_in; (void)out_size;

    const float* query   = (const float*)d_in[0];
    const float* key     = (const float*)d_in[1];
    const float* value   = (const float*)d_in[2];
    const float* wq      = (const float*)d_in[3];
    const float* bq      = (const float*)d_in[4];
    const float* wk      = (const float*)d_in[5];
    const float* bk      = (const float*)d_in[6];
    const float* wv      = (const float*)d_in[7];
    const float* bv      = (const float*)d_in[8];
    const float* wo      = (const float*)d_in[9];
    const float* bo      = (const float*)d_in[10];
    const float* q_theta = (const float*)d_in[11];
    const float* q_phi   = (const float*)d_in[12];
    const float* q_preW  = (const float*)d_in[13];
    const float* q_preb  = (const float*)d_in[14];
    const float* q_postW = (const float*)d_in[15];
    const float* q_postb = (const float*)d_in[16];
    const float* k_theta = (const float*)d_in[17];
    const float* k_phi   = (const float*)d_in[18];
    const float* k_preW  = (const float*)d_in[19];
    const float* k_preb  = (const float*)d_in[20];
    const float* k_postW = (const float*)d_in[21];
    const float* k_postb = (const float*)d_in[22];
    float* out = (float*)d_out;

    float *pWq, *pWk, *pbq, *pbk, *pMq, *pMk, *pQ, *pK, *pV, *pO;
    cudaGetSymbolAddress((void**)&pWq, g_Wq);
    cudaGetSymbolAddress((void**)&pWk, g_Wk);
    cudaGetSymbolAddress((void**)&pbq, g_bq);
    cudaGetSymbolAddress((void**)&pbk, g_bk);
    cudaGetSymbolAddress((void**)&pMq, g_Mq);
    cudaGetSymbolAddress((void**)&pMk, g_Mk);
    cudaGetSymbolAddress((void**)&pQ,  g_Q);
    cudaGetSymbolAddress((void**)&pK,  g_K);
    cudaGetSymbolAddress((void**)&pV,  g_V);
    cudaGetSymbolAddress((void**)&pO,  g_O);

    // 1) Build effective quantum operators (tiny)
    build_eff_kernel<<<1, 64>>>(q_theta, q_phi, q_preW, q_preb, q_postW, q_postb,
                                bq, pMq, pbq);
    build_eff_kernel<<<1, 64>>>(k_theta, k_phi, k_preW, k_preb, k_postW, k_postb,
                                bk, pMk, pbk);

    // 2) Fold into projection weights (tiny)
    fold_weights_kernel<<<dim3(HEADS, E_DIM/256), 256>>>(wq, pMq, pWq);
    fold_weights_kernel<<<dim3(HEADS, E_DIM/256), 256>>>(wk, pMk, pWk);

    // 3) QKV projections (head-major output layout)
    dim3 ggrid(E_DIM/128, ROWS/128);
    sgemm_bias_kernel<<<ggrid, 256>>>(query, pWq, pbq, pQ, 1);
    sgemm_bias_kernel<<<ggrid, 256>>>(key,   pWk, pbk, pK, 1);
    sgemm_bias_kernel<<<ggrid, 256>>>(value, wv,  bv,  pV, 1);

    // 4) Flash attention
    const int smem_flash = (64*64 + 64*KV_STRIDE + 64*64) * (int)sizeof(float);
    cudaFuncSetAttribute(flash_attn_kernel,
                         cudaFuncAttributeMaxDynamicSharedMemorySize, smem_flash);
    flash_attn_kernel<<<dim3(SEQ/64, BATCH*HEADS), 256, smem_flash>>>(pQ, pK, pV, pO);

    // 5) Output projection
    sgemm_bias_kernel<<<ggrid, 256>>>(pO, wo, bo, out, 0);
}

// round 6
// speedup vs baseline: 1.9920x; 1.9920x over previous
#include <cuda_runtime.h>
#include <cuda_bf16.h>
#include <cstdint>

// Problem constants
#define E_DIM   1024
#define HEADS   16
#define HDIM    64
#define BATCH   4
#define SEQ     2048
#define ROWS    (BATCH*SEQ)        // 8192
#define NQUBITS 6

// ---------------- bf16 mma.sync helpers (baseline PTX, sm_80+) -------------
__device__ __forceinline__ void mma_bf16(
    float* d, const uint32_t* a, const uint32_t* b)
{
    asm volatile(
        "mma.sync.aligned.m16n8k16.row.col.f32.bf16.bf16.f32 "
        "{%0,%1,%2,%3}, {%4,%5,%6,%7}, {%8,%9}, {%0,%1,%2,%3};"
        : "+f"(d[0]), "+f"(d[1]), "+f"(d[2]), "+f"(d[3])
        : "r"(a[0]), "r"(a[1]), "r"(a[2]), "r"(a[3]), "r"(b[0]), "r"(b[1]));
}

// Split two floats into packed bf16 hi-word and lo-word (two-term expansion).
__device__ __forceinline__ void split2(float x, float y,
                                       uint32_t& hw, uint32_t& lw)
{
    __nv_bfloat16 hx = __float2bfloat16(x);
    __nv_bfloat16 hy = __float2bfloat16(y);
    float rx = x - __bfloat162float(hx);
    float ry = y - __bfloat162float(hy);
    __nv_bfloat162 h2; h2.x = hx; h2.y = hy;
    __nv_bfloat162 l2; l2.x = __float2bfloat16(rx); l2.y = __float2bfloat16(ry);
    hw = *reinterpret_cast<uint32_t*>(&h2);
    lw = *reinterpret_cast<uint32_t*>(&l2);
}
__device__ __forceinline__ void split1(float x, __nv_bfloat16& h, __nv_bfloat16& l)
{
    h = __float2bfloat16(x);
    l = __float2bfloat16(x - __bfloat162float(h));
}

// ---------------- device scratch ----------------
__device__ float g_Wq[E_DIM*E_DIM];
__device__ float g_Wk[E_DIM*E_DIM];
__device__ float g_bq[E_DIM];
__device__ float g_bk[E_DIM];
__device__ float g_Mq[HDIM*HDIM];
__device__ float g_Mk[HDIM*HDIM];
__device__ float g_Q[(size_t)ROWS*E_DIM];
__device__ float g_K[(size_t)ROWS*E_DIM];
__device__ float g_V[(size_t)ROWS*E_DIM];
__device__ float g_O[(size_t)ROWS*E_DIM];

// ============================================================================
// Kernel 1: build effective quantum operator (tiny, exact fp32).
// ============================================================================
__global__ void build_eff_kernel(
    const float* __restrict__ theta, const float* __restrict__ phi,
    const float* __restrict__ preW,  const float* __restrict__ preb,
    const float* __restrict__ postW, const float* __restrict__ postb,
    const float* __restrict__ b_in,
    float* __restrict__ Meff, float* __restrict__ beff)
{
    __shared__ float R[HDIM][HDIM];
    __shared__ float T[HDIM][HDIM];
    __shared__ float rb[HDIM];
    __shared__ float ctb[NQUBITS], stb[NQUBITS], cpb[NQUBITS];

    const int t = threadIdx.x;   // 0..63
    if (t < NQUBITS) {
        ctb[t] = cosf(theta[t]);
        stb[t] = sinf(theta[t]);
        cpb[t] = cosf(phi[t]);
    }
    __syncthreads();

    float v[HDIM];
    for (int i = 0; i < HDIM; i++) v[i] = (i == t) ? 1.f : 0.f;
    for (int q = 0; q < NQUBITS; q++) {
        const int mask = 1 << q;
        const float c = ctb[q], s = stb[q], p = cpb[q];
        for (int i0 = 0; i0 < HDIM; i0++) {
            if (i0 & mask) continue;
            const int i1 = i0 | mask;
            float x0 = v[i0], x1 = v[i1];
            v[i0] = c * x0 - s * x1;
            v[i1] = (s * x0 + c * x1) * p;
        }
    }
    for (int i = 0; i < HDIM; i++) R[i][t] = v[i];
    __syncthreads();

    for (int i = 0; i < HDIM; i++) {
        float acc = 0.f;
        for (int k = 0; k < HDIM; k++) acc += R[i][k] * preW[k*HDIM + t];
        T[i][t] = acc;
    }
    __syncthreads();

    for (int i = 0; i < HDIM; i++) {
        float acc = (i == t) ? 1.f : 0.f;
        for (int k = 0; k < HDIM; k++) acc += postW[i*HDIM + k] * T[k][t];
        Meff[i*HDIM + t] = acc;
    }

    {
        float acc = 0.f;
        for (int j = 0; j < HDIM; j++) acc += R[t][j] * preb[j];
        rb[t] = acc;
    }
    __syncthreads();

    float ce = postb[t];
    for (int k = 0; k < HDIM; k++) ce += postW[t*HDIM + k] * rb[k];

    __syncthreads();

    for (int h = 0; h < HEADS; h++) {
        float b = ce;
        for (int j = 0; j < HDIM; j++) b += Meff[t*HDIM + j] * b_in[h*HDIM + j];
        beff[h*HDIM + t] = b;
    }
}

// ============================================================================
// Kernel 2: fold Meff into projection weights (exact fp32).
// ============================================================================
__global__ __launch_bounds__(256) void fold_weights_kernel(
    const float* __restrict__ W, const float* __restrict__ Meff,
    float* __restrict__ Weff)
{
    __shared__ float Ms[HDIM*HDIM];
    const int h  = blockIdx.x;
    const int e  = blockIdx.y * 64 + (threadIdx.x & 63);
    const int ig = threadIdx.x >> 6;
    for (int p = threadIdx.x; p < HDIM*HDIM; p += 256) Ms[p] = Meff[p];
    __syncthreads();

    float acc[16];
    #pragma unroll
    for (int i = 0; i < 16; i++) acc[i] = 0.f;

    for (int j = 0; j < HDIM; j++) {
        const float w = W[(size_t)(h*HDIM + j) * E_DIM + e];
        #pragma unroll
        for (int i = 0; i < 16; i++) acc[i] += Ms[(ig*16 + i)*HDIM + j] * w;
    }
    #pragma unroll
    for (int i = 0; i < 16; i++)
        Weff[(size_t)(h*HDIM + ig*16 + i) * E_DIM + e] = acc[i];
}

// ============================================================================
// Kernel 3: bf16x3-compensated GEMM + bias. C[m,n] = sum_k A[m,k]*W[n,k]+bias
// 128x128 CTA tile, 8 warps (warp 64x32), K-chunk 32 (16 packed-pair words),
// hi/lo bf16 smem arrays, double-buffered. acc += Ah*Bh + Al*Bh + Ah*Bl.
// Stride 20 (==4 mod 32) -> conflict-free fragment loads.
// ============================================================================
#define PSTR 20
#define PBUF (128*PSTR)                 // 2560 words per array per buffer

__global__ __launch_bounds__(256) void bf16x3_gemm_kernel(
    const float* __restrict__ A, const float* __restrict__ W,
    const float* __restrict__ bias, float* __restrict__ C, int layout)
{
    extern __shared__ uint32_t su[];
    uint32_t* Ah = su;                  // [2][128][PSTR]
    uint32_t* Al = su + 2*PBUF;
    uint32_t* Bh = su + 4*PBUF;
    uint32_t* Bl = su + 6*PBUF;

    const int tid  = threadIdx.x;
    const int wid  = tid >> 5, lane = tid & 31;
    const int wm   = (wid >> 2) * 64;
    const int wn   = (wid & 3) * 32;
    const int m0   = blockIdx.y * 128;
    const int n0   = blockIdx.x * 128;
    const int lr4  = lane >> 2;
    const int lc4  = lane & 3;

    int grow[4], gseg[4];
    #pragma unroll
    for (int i = 0; i < 4; i++) {
        const int idx = tid + i * 256;
        grow[i] = idx >> 3;
        gseg[i] = idx & 7;
    }

    float4 pa[4], pb[4];
    auto ldg = [&](int c) {
        #pragma unroll
        for (int i = 0; i < 4; i++) {
            pa[i] = *(const float4*)(A + (size_t)(m0 + grow[i]) * E_DIM + c*32 + gseg[i]*4);
            pb[i] = *(const float4*)(W + (size_t)(n0 + grow[i]) * E_DIM + c*32 + gseg[i]*4);
        }
    };
    auto sts = [&](int buf) {
        #pragma unroll
        for (int i = 0; i < 4; i++) {
            const int off = buf*PBUF + grow[i]*PSTR + gseg[i]*2;
            uint32_t h0, l0, h1, l1;
            split2(pa[i].x, pa[i].y, h0, l0);
            split2(pa[i].z, pa[i].w, h1, l1);
            Ah[off] = h0; Ah[off+1] = h1;
            Al[off] = l0; Al[off+1] = l1;
            split2(pb[i].x, pb[i].y, h0, l0);
            split2(pb[i].z, pb[i].w, h1, l1);
            Bh[off] = h0; Bh[off+1] = h1;
            Bl[off] = l0; Bl[off+1] = l1;
        }
    };

    float acc[4][4][4];
    #pragma unroll
    for (int mi = 0; mi < 4; mi++)
        #pragma unroll
        for (int ni = 0; ni < 4; ni++)
            #pragma unroll
            for (int r = 0; r < 4; r++) acc[mi][ni][r] = 0.f;

    ldg(0); sts(0); __syncthreads();

    const int NCHUNK = E_DIM / 32;      // 32
    #pragma unroll 1
    for (int c = 0; c < NCHUNK; c++) {
        const int buf = c & 1;
        if (c + 1 < NCHUNK) ldg(c + 1);

        const uint32_t* Abh = Ah + buf*PBUF;
        const uint32_t* Abl = Al + buf*PBUF;
        const uint32_t* Bbh = Bh + buf*PBUF;
        const uint32_t* Bbl = Bl + buf*PBUF;
        #pragma unroll
        for (int ks = 0; ks < 2; ks++) {       // 2 x K16 = 32
            const int kc = ks*8 + lc4;
            uint32_t ah[4][4], al[4][4];
            #pragma unroll
            for (int mi = 0; mi < 4; mi++) {
                const int r = wm + mi*16 + lr4;
                ah[mi][0] = Abh[r*PSTR + kc];
                ah[mi][1] = Abh[(r+8)*PSTR + kc];
                ah[mi][2] = Abh[r*PSTR + kc + 4];
                ah[mi][3] = Abh[(r+8)*PSTR + kc + 4];
                al[mi][0] = Abl[r*PSTR + kc];
                al[mi][1] = Abl[(r+8)*PSTR + kc];
                al[mi][2] = Abl[r*PSTR + kc + 4];
                al[mi][3] = Abl[(r+8)*PSTR + kc + 4];
            }
            #pragma unroll
            for (int ni = 0; ni < 4; ni++) {
                const int rn = wn + ni*8 + lr4;
                uint32_t bh[2], bl[2];
                bh[0] = Bbh[rn*PSTR + kc];
                bh[1] = Bbh[rn*PSTR + kc + 4];
                bl[0] = Bbl[rn*PSTR + kc];
                bl[1] = Bbl[rn*PSTR + kc + 4];
                #pragma unroll
                for (int mi = 0; mi < 4; mi++) {
                    mma_bf16(acc[mi][ni], ah[mi], bh);
                    mma_bf16(acc[mi][ni], al[mi], bh);
                    mma_bf16(acc[mi][ni], ah[mi], bl);
                }
            }
        }

        if (c + 1 < NCHUNK) { sts((c + 1) & 1); __syncthreads(); }
    }

    // epilogue
    if (layout == 0) {
        #pragma unroll
        for (int ni = 0; ni < 4; ni++) {
            const int n = n0 + wn + ni*8 + 2*lc4;
            const float b0 = bias[n], b1 = bias[n+1];
            #pragma unroll
            for (int mi = 0; mi < 4; mi++) {
                #pragma unroll
                for (int half = 0; half < 2; half++) {
                    const int m = m0 + wm + mi*16 + lr4 + half*8;
                    float2 o;
                    o.x = acc[mi][ni][half*2+0] + b0;
                    o.y = acc[mi][ni][half*2+1] + b1;
                    *(float2*)(C + (size_t)m * E_DIM + n) = o;
                }
            }
        }
    } else {
        #pragma unroll
        for (int ni = 0; ni < 4; ni++) {
            const int n = n0 + wn + ni*8 + 2*lc4;
            const float b0 = bias[n], b1 = bias[n+1];
            const int h = n >> 6, dd = n & 63;
            #pragma unroll
            for (int mi = 0; mi < 4; mi++) {
                #pragma unroll
                for (int half = 0; half < 2; half++) {
                    const int m = m0 + wm + mi*16 + lr4 + half*8;
                    const int b = m >> 11, s2 = m & 2047;
                    float2 o;
                    o.x = acc[mi][ni][half*2+0] + b0;
                    o.y = acc[mi][ni][half*2+1] + b1;
                    *(float2*)(C + ((size_t)(b*HEADS + h) * SEQ + s2) * HDIM + dd) = o;
                }
            }
        }
    }
}

// ============================================================================
// Kernel 4: flash attention, bf16x3 compensated mma. Br=128, Bc=64, Dh=64.
// 8 warps, each owns 16 q-rows -> warp-local softmax. Stride 36 (==4 mod 32).
// V stored transposed (dh-major) for the PV B-operand.
// ============================================================================
#define FSTR 36
#define QH_OFF 0
#define QL_OFF (128*FSTR)                 // 4608
#define KH_OFF (QL_OFF + 128*FSTR)        // 9216
#define KL_OFF (KH_OFF + 64*FSTR)         // 11520
#define VH_OFF (KL_OFF + 64*FSTR)         // 13824
#define VL_OFF (VH_OFF + 64*FSTR)         // 16128
#define PH_OFF (VL_OFF + 64*FSTR)         // 18432
#define PL_OFF (PH_OFF + 128*FSTR)        // 23040
#define FA_WORDS (PL_OFF + 128*FSTR)      // 27648 words = 110592 B

__global__ __launch_bounds__(256) void flash_attn_kernel(
    const float* __restrict__ Q, const float* __restrict__ K,
    const float* __restrict__ V, float* __restrict__ O)
{
    extern __shared__ uint32_t su[];
    uint32_t* Qh = su + QH_OFF;
    uint32_t* Ql = su + QL_OFF;
    uint32_t* Kh = su + KH_OFF;
    uint32_t* Kl = su + KL_OFF;
    uint32_t* Vth = su + VH_OFF;
    uint32_t* Vtl = su + VL_OFF;
    uint32_t* Ph = su + PH_OFF;
    uint32_t* Pl = su + PL_OFF;
    __nv_bfloat16* VthH = (__nv_bfloat16*)Vth;
    __nv_bfloat16* VtlH = (__nv_bfloat16*)Vtl;

    const int tid = threadIdx.x;
    const int wid = tid >> 5, lane = tid & 31;
    const int lr4 = lane >> 2, lc4 = lane & 3;
    const int bh = blockIdx.y;
    const int q0 = blockIdx.x * 128;

    const float* Qg = Q + (size_t)bh * SEQ * HDIM;
    const float* Kg = K + (size_t)bh * SEQ * HDIM;
    const float* Vg = V + (size_t)bh * SEQ * HDIM;

    // Load Q tile (pre-scaled by 1/8), split hi/lo, packed pairs
    #pragma unroll
    for (int it = 0; it < 8; it++) {
        const int idx = tid + it * 256;       // 0..2047
        const int r = idx >> 4;
        const int d = (idx & 15) * 4;
        float4 v = *(const float4*)(Qg + (size_t)(q0 + r) * HDIM + d);
        const int off = r*FSTR + (d >> 1);
        uint32_t h0, l0, h1, l1;
        split2(v.x * 0.125f, v.y * 0.125f, h0, l0);
        split2(v.z * 0.125f, v.w * 0.125f, h1, l1);
        Qh[off] = h0; Qh[off+1] = h1;
        Ql[off] = l0; Ql[off+1] = l1;
    }

    float m0 = -1e30f, m1 = -1e30f, l0r = 0.f, l1r = 0.f;
    float o[8][4];
    #pragma unroll
    for (int ni = 0; ni < 8; ni++)
        #pragma unroll
        for (int r = 0; r < 4; r++) o[ni][r] = 0.f;

    const int rA = wid*16 + lr4;

    #pragma unroll 1
    for (int kt = 0; kt < SEQ/64; kt++) {
        __syncthreads();
        const int n0 = kt * 64;
        #pragma unroll
        for (int it = 0; it < 4; it++) {
            const int idx = tid + it * 256;   // 0..1023
            const int r = idx >> 4;
            const int d = (idx & 15) * 4;
            float4 kv = *(const float4*)(Kg + (size_t)(n0 + r) * HDIM + d);
            float4 vv = *(const float4*)(Vg + (size_t)(n0 + r) * HDIM + d);
            const int off = r*FSTR + (d >> 1);
            uint32_t h0, l0, h1, l1;
            split2(kv.x, kv.y, h0, l0);
            split2(kv.z, kv.w, h1, l1);
            Kh[off] = h0; Kh[off+1] = h1;
            Kl[off] = l0; Kl[off+1] = l1;
            // V transposed: element (kv-row r, dh d+j) -> Vt[d+j][pair r/2, half r&1]
            const float vvv[4] = {vv.x, vv.y, vv.z, vv.w};
            #pragma unroll
            for (int j = 0; j < 4; j++) {
                __nv_bfloat16 hb, lb;
                split1(vvv[j], hb, lb);
                const int hoff = ((d+j)*FSTR + (r >> 1))*2 + (r & 1);
                VthH[hoff] = hb;
                VtlH[hoff] = lb;
            }
        }
        __syncthreads();

        // S = Q @ K^T  (bf16x3)
        float s[8][4];
        #pragma unroll
        for (int ni = 0; ni < 8; ni++)
            #pragma unroll
            for (int r = 0; r < 4; r++) s[ni][r] = 0.f;

        #pragma unroll
        for (int ks = 0; ks < 4; ks++) {
            const int kc = ks*8 + lc4;
            uint32_t ah[4], al[4];
            ah[0] = Qh[rA*FSTR + kc];
            ah[1] = Qh[(rA+8)*FSTR + kc];
            ah[2] = Qh[rA*FSTR + kc + 4];
            ah[3] = Qh[(rA+8)*FSTR + kc + 4];
            al[0] = Ql[rA*FSTR + kc];
            al[1] = Ql[(rA+8)*FSTR + kc];
            al[2] = Ql[rA*FSTR + kc + 4];
            al[3] = Ql[(rA+8)*FSTR + kc + 4];
            #pragma unroll
            for (int ni = 0; ni < 8; ni++) {
                const int n = ni*8 + lr4;
                uint32_t bh2[2], bl2[2];
                bh2[0] = Kh[n*FSTR + kc];
                bh2[1] = Kh[n*FSTR + kc + 4];
                bl2[0] = Kl[n*FSTR + kc];
                bl2[1] = Kl[n*FSTR + kc + 4];
                mma_bf16(s[ni], ah, bh2);
                mma_bf16(s[ni], al, bh2);
                mma_bf16(s[ni], ah, bl2);
            }
        }

        // online softmax (warp-local rows)
        float v0 = -1e30f, v1 = -1e30f;
        #pragma unroll
        for (int ni = 0; ni < 8; ni++) {
            v0 = fmaxf(v0, fmaxf(s[ni][0], s[ni][1]));
            v1 = fmaxf(v1, fmaxf(s[ni][2], s[ni][3]));
        }
        v0 = fmaxf(v0, __shfl_xor_sync(0xffffffffu, v0, 1));
        v0 = fmaxf(v0, __shfl_xor_sync(0xffffffffu, v0, 2));
        v1 = fmaxf(v1, __shfl_xor_sync(0xffffffffu, v1, 1));
        v1 = fmaxf(v1, __shfl_xor_sync(0xffffffffu, v1, 2));
        const float mn0 = fmaxf(m0, v0), mn1 = fmaxf(m1, v1);
        const float al0 = __expf(m0 - mn0), al1 = __expf(m1 - mn1);
        m0 = mn0; m1 = mn1;

        float rs0 = 0.f, rs1 = 0.f;
        #pragma unroll
        for (int ni = 0; ni < 8; ni++) {
            s[ni][0] = __expf(s[ni][0] - mn0);
            s[ni][1] = __expf(s[ni][1] - mn0);
            s[ni][2] = __expf(s[ni][2] - mn1);
            s[ni][3] = __expf(s[ni][3] - mn1);
            rs0 += s[ni][0] + s[ni][1];
            rs1 += s[ni][2] + s[ni][3];
        }
        rs0 += __shfl_xor_sync(0xffffffffu, rs0, 1);
        rs0 += __shfl_xor_sync(0xffffffffu, rs0, 2);
        rs1 += __shfl_xor_sync(0xffffffffu, rs1, 1);
        rs1 += __shfl_xor_sync(0xffffffffu, rs1, 2);
        l0r = l0r * al0 + rs0;
        l1r = l1r * al1 + rs1;
        #pragma unroll
        for (int ni = 0; ni < 8; ni++) {
            o[ni][0] *= al0; o[ni][1] *= al0;
            o[ni][2] *= al1; o[ni][3] *= al1;
        }

        // write P hi/lo (own-warp rows; pairs align with registers)
        #pragma unroll
        for (int ni = 0; ni < 8; ni++) {
            const int wc = ni*4 + lc4;
            uint32_t hw, lw;
            split2(s[ni][0], s[ni][1], hw, lw);
            Ph[rA*FSTR + wc] = hw; Pl[rA*FSTR + wc] = lw;
            split2(s[ni][2], s[ni][3], hw, lw);
            Ph[(rA+8)*FSTR + wc] = hw; Pl[(rA+8)*FSTR + wc] = lw;
        }
        __syncwarp();

        // O += P @ V  (bf16x3, B = V transposed)
        #pragma unroll
        for (int ks = 0; ks < 4; ks++) {
            const int kc = ks*8 + lc4;
            uint32_t ah[4], al[4];
            ah[0] = Ph[rA*FSTR + kc];
            ah[1] = Ph[(rA+8)*FSTR + kc];
            ah[2] = Ph[rA*FSTR + kc + 4];
            ah[3] = Ph[(rA+8)*FSTR + kc + 4];
            al[0] = Pl[rA*FSTR + kc];
            al[1] = Pl[(rA+8)*FSTR + kc];
            al[2] = Pl[rA*FSTR + kc + 4];
            al[3] = Pl[(rA+8)*FSTR + kc + 4];
            #pragma unroll
            for (int ni = 0; ni < 8; ni++) {
                const int n = ni*8 + lr4;    // dh index
                uint32_t bh2[2], bl2[2];
                bh2[0] = Vth[n*FSTR + kc];
                bh2[1] = Vth[n*FSTR + kc + 4];
                bl2[0] = Vtl[n*FSTR + kc];
                bl2[1] = Vtl[n*FSTR + kc + 4];
                mma_bf16(o[ni], ah, bh2);
                mma_bf16(o[ni], al, bh2);
                mma_bf16(o[ni], ah, bl2);
            }
        }
    }

    // epilogue: normalize, write (B,S,E)
    const int b = bh >> 4, h = bh & 15;
    const float inv0 = 1.f / l0r, inv1 = 1.f / l1r;
    #pragma unroll
    for (int ni = 0; ni < 8; ni++) {
        const int d = h*HDIM + ni*8 + 2*lc4;
        const int r = q0 + rA;
        float2 w0 = make_float2(o[ni][0]*inv0, o[ni][1]*inv0);
        float2 w1 = make_float2(o[ni][2]*inv1, o[ni][3]*inv1);
        *(float2*)(O + ((size_t)b*SEQ + r) * E_DIM + d)     = w0;
        *(float2*)(O + ((size_t)b*SEQ + r + 8) * E_DIM + d) = w1;
    }
}

// ============================================================================
// Host launcher
// ============================================================================
extern "C" void kernel_launch(void* const* d_in, const int* in_sizes, int n_in,
                              void* d_out, int out_size)
{
    (void)in_sizes; (void)n_in; (void)out_size;

    const float* query   = (const float*)d_in[0];
    const float* key     = (const float*)d_in[1];
    const float* value   = (const float*)d_in[2];
    const float* wq      = (const float*)d_in[3];
    const float* bq      = (const float*)d_in[4];
    const float* wk      = (const float*)d_in[5];
    const float* bk      = (const float*)d_in[6];
    const float* wv      = (const float*)d_in[7];
    const float* bv      = (const float*)d_in[8];
    const float* wo      = (const float*)d_in[9];
    const float* bo      = (const float*)d_in[10];
    const float* q_theta = (const float*)d_in[11];
    const float* q_phi   = (const float*)d_in[12];
    const float* q_preW  = (const float*)d_in[13];
    const float* q_preb  = (const float*)d_in[14];
    const float* q_postW = (const float*)d_in[15];
    const float* q_postb = (const float*)d_in[16];
    const float* k_theta = (const float*)d_in[17];
    const float* k_phi   = (const float*)d_in[18];
    const float* k_preW  = (const float*)d_in[19];
    const float* k_preb  = (const float*)d_in[20];
    const float* k_postW = (const float*)d_in[21];
    const float* k_postb = (const float*)d_in[22];
    float* out = (float*)d_out;

    float *pWq, *pWk, *pbq, *pbk, *pMq, *pMk, *pQ, *pK, *pV, *pO;
    cudaGetSymbolAddress((void**)&pWq, g_Wq);
    cudaGetSymbolAddress((void**)&pWk, g_Wk);
    cudaGetSymbolAddress((void**)&pbq, g_bq);
    cudaGetSymbolAddress((void**)&pbk, g_bk);
    cudaGetSymbolAddress((void**)&pMq, g_Mq);
    cudaGetSymbolAddress((void**)&pMk, g_Mk);
    cudaGetSymbolAddress((void**)&pQ,  g_Q);
    cudaGetSymbolAddress((void**)&pK,  g_K);
    cudaGetSymbolAddress((void**)&pV,  g_V);
    cudaGetSymbolAddress((void**)&pO,  g_O);

    // 1) Build effective quantum operators
    build_eff_kernel<<<1, 64>>>(q_theta, q_phi, q_preW, q_preb, q_postW, q_postb,
                                bq, pMq, pbq);
    build_eff_kernel<<<1, 64>>>(k_theta, k_phi, k_preW, k_preb, k_postW, k_postb,
                                bk, pMk, pbk);

    // 2) Fold into projection weights
    fold_weights_kernel<<<dim3(HEADS, E_DIM/64), 256>>>(wq, pMq, pWq);
    fold_weights_kernel<<<dim3(HEADS, E_DIM/64), 256>>>(wk, pMk, pWk);

    // 3) QKV projections via bf16x3 mma (head-major output layout)
    const int gemm_smem = 8 * PBUF * (int)sizeof(uint32_t);   // 81920
    cudaFuncSetAttribute(bf16x3_gemm_kernel,
                         cudaFuncAttributeMaxDynamicSharedMemorySize, gemm_smem);
    dim3 ggrid(E_DIM/128, ROWS/128);
    bf16x3_gemm_kernel<<<ggrid, 256, gemm_smem>>>(query, pWq, pbq, pQ, 1);
    bf16x3_gemm_kernel<<<ggrid, 256, gemm_smem>>>(key,   pWk, pbk, pK, 1);
    bf16x3_gemm_kernel<<<ggrid, 256, gemm_smem>>>(value, wv,  bv,  pV, 1);

    // 4) Flash attention (bf16x3 mma)
    const int fa_smem = FA_WORDS * (int)sizeof(uint32_t);     // 110592
    cudaFuncSetAttribute(flash_attn_kernel,
                         cudaFuncAttributeMaxDynamicSharedMemorySize, fa_smem);
    flash_attn_kernel<<<dim3(SEQ/128, BATCH*HEADS), 256, fa_smem>>>(pQ, pK, pV, pO);

    // 5) Output projection
    bf16x3_gemm_kernel<<<ggrid, 256, gemm_smem>>>(pO, wo, bo, out, 0);
}

// round 7
// speedup vs baseline: 2.3674x; 1.1884x over previous
#include <cuda_runtime.h>
#include <cuda_bf16.h>
#include <cstdint>

// Problem constants
#define E_DIM   1024
#define HEADS   16
#define HDIM    64
#define BATCH   4
#define SEQ     2048
#define ROWS    (BATCH*SEQ)        // 8192
#define NQUBITS 6
#define EW      (E_DIM/2)          // 512 packed words per E row
#define DW      (HDIM/2)           // 32 packed words per head row

// ---------------- helpers ----------------
__device__ __forceinline__ void mma_bf16(
    float* d, const uint32_t* a, const uint32_t* b)
{
    asm volatile(
        "mma.sync.aligned.m16n8k16.row.col.f32.bf16.bf16.f32 "
        "{%0,%1,%2,%3}, {%4,%5,%6,%7}, {%8,%9}, {%0,%1,%2,%3};"
        : "+f"(d[0]), "+f"(d[1]), "+f"(d[2]), "+f"(d[3])
        : "r"(a[0]), "r"(a[1]), "r"(a[2]), "r"(a[3]), "r"(b[0]), "r"(b[1]));
}
__device__ __forceinline__ void split2(float x, float y,
                                       uint32_t& hw, uint32_t& lw)
{
    __nv_bfloat16 hx = __float2bfloat16(x);
    __nv_bfloat16 hy = __float2bfloat16(y);
    __nv_bfloat162 h2; h2.x = hx; h2.y = hy;
    __nv_bfloat162 l2;
    l2.x = __float2bfloat16(x - __bfloat162float(hx));
    l2.y = __float2bfloat16(y - __bfloat162float(hy));
    hw = *reinterpret_cast<uint32_t*>(&h2);
    lw = *reinterpret_cast<uint32_t*>(&l2);
}
__device__ __forceinline__ uint32_t sptr(const void* p) {
    return (uint32_t)__cvta_generic_to_shared(p);
}
__device__ __forceinline__ void cp16(uint32_t dst, const void* src) {
    asm volatile("cp.async.cg.shared.global [%0], [%1], 16;" :: "r"(dst), "l"(src));
}
#define CP_COMMIT() asm volatile("cp.async.commit_group;" ::: "memory")
#define CP_WAIT0()  asm volatile("cp.async.wait_group 0;" ::: "memory")
__device__ __forceinline__ void ldmx4(uint32_t* r, uint32_t addr) {
    asm volatile("ldmatrix.sync.aligned.m8n8.x4.shared.b16 {%0,%1,%2,%3}, [%4];"
        : "=r"(r[0]), "=r"(r[1]), "=r"(r[2]), "=r"(r[3]) : "r"(addr));
}

// ---------------- device scratch ----------------
__device__ float    g_Mq[HDIM*HDIM];
__device__ float    g_Mk[HDIM*HDIM];
__device__ float    g_bq[E_DIM];
__device__ float    g_bk[E_DIM];
__device__ uint32_t g_Wqh[E_DIM*EW], g_Wql[E_DIM*EW];
__device__ uint32_t g_Wkh[E_DIM*EW], g_Wkl[E_DIM*EW];
__device__ uint32_t g_Wvh[E_DIM*EW], g_Wvl[E_DIM*EW];
__device__ uint32_t g_Woh[E_DIM*EW], g_Wol[E_DIM*EW];
__device__ uint32_t g_Xqh[(size_t)ROWS*EW], g_Xql[(size_t)ROWS*EW];
__device__ uint32_t g_Xkh[(size_t)ROWS*EW], g_Xkl[(size_t)ROWS*EW];
__device__ uint32_t g_Xvh[(size_t)ROWS*EW], g_Xvl[(size_t)ROWS*EW];
__device__ uint32_t g_Qh[(size_t)ROWS*EW],  g_Ql[(size_t)ROWS*EW];
__device__ uint32_t g_Kh[(size_t)ROWS*EW],  g_Kl[(size_t)ROWS*EW];
__device__ float    g_Vf[(size_t)ROWS*E_DIM];
__device__ uint32_t g_Vth[(size_t)64*HDIM*(SEQ/2)], g_Vtl[(size_t)64*HDIM*(SEQ/2)];
__device__ uint32_t g_Oh[(size_t)ROWS*EW],  g_Ol[(size_t)ROWS*EW];

// ============================================================================
// Kernel 1: build effective quantum operator (tiny, exact fp32).
// ============================================================================
__global__ void build_eff_kernel(
    const float* __restrict__ theta, const float* __restrict__ phi,
    const float* __restrict__ preW,  const float* __restrict__ preb,
    const float* __restrict__ postW, const float* __restrict__ postb,
    const float* __restrict__ b_in,
    float* __restrict__ Meff, float* __restrict__ beff)
{
    __shared__ float R[HDIM][HDIM];
    __shared__ float T[HDIM][HDIM];
    __shared__ float rb[HDIM];
    __shared__ float ctb[NQUBITS], stb[NQUBITS], cpb[NQUBITS];

    const int t = threadIdx.x;
    if (t < NQUBITS) {
        ctb[t] = cosf(theta[t]);
        stb[t] = sinf(theta[t]);
        cpb[t] = cosf(phi[t]);
    }
    __syncthreads();

    float v[HDIM];
    for (int i = 0; i < HDIM; i++) v[i] = (i == t) ? 1.f : 0.f;
    for (int q = 0; q < NQUBITS; q++) {
        const int mask = 1 << q;
        const float c = ctb[q], s = stb[q], p = cpb[q];
        for (int i0 = 0; i0 < HDIM; i0++) {
            if (i0 & mask) continue;
            const int i1 = i0 | mask;
            float x0 = v[i0], x1 = v[i1];
            v[i0] = c * x0 - s * x1;
            v[i1] = (s * x0 + c * x1) * p;
        }
    }
    for (int i = 0; i < HDIM; i++) R[i][t] = v[i];
    __syncthreads();

    for (int i = 0; i < HDIM; i++) {
        float acc = 0.f;
        for (int k = 0; k < HDIM; k++) acc += R[i][k] * preW[k*HDIM + t];
        T[i][t] = acc;
    }
    __syncthreads();

    for (int i = 0; i < HDIM; i++) {
        float acc = (i == t) ? 1.f : 0.f;
        for (int k = 0; k < HDIM; k++) acc += postW[i*HDIM + k] * T[k][t];
        Meff[i*HDIM + t] = acc;
    }

    {
        float acc = 0.f;
        for (int j = 0; j < HDIM; j++) acc += R[t][j] * preb[j];
        rb[t] = acc;
    }
    __syncthreads();

    float ce = postb[t];
    for (int k = 0; k < HDIM; k++) ce += postW[t*HDIM + k] * rb[k];
    __syncthreads();

    for (int h = 0; h < HEADS; h++) {
        float b = ce;
        for (int j = 0; j < HDIM; j++) b += Meff[t*HDIM + j] * b_in[h*HDIM + j];
        beff[h*HDIM + t] = b;
    }
}

// ============================================================================
// Kernel 2: fold Meff into weights AND split-pack to bf16 hi/lo.
//   Weff[h*64+i, e] = sum_j Meff[i][j] * W[h*64+j, e]
// grid (16 h, 16 e-blocks of 64), block 256: 32 e-pairs x 8 row-groups.
// ============================================================================
__global__ __launch_bounds__(256) void fold_split_kernel(
    const float* __restrict__ W, const float* __restrict__ Meff,
    uint32_t* __restrict__ Wh, uint32_t* __restrict__ Wl)
{
    __shared__ float Ms[HDIM*HDIM];
    const int h  = blockIdx.x;
    const int eb = blockIdx.y;
    const int ep = threadIdx.x & 31;      // e-pair in block
    const int ig = threadIdx.x >> 5;      // 0..7 row group
    for (int p = threadIdx.x; p < HDIM*HDIM; p += 256) Ms[p] = Meff[p];
    __syncthreads();

    const int e = eb*64 + ep*2;
    float acc[8][2];
    #pragma unroll
    for (int i = 0; i < 8; i++) { acc[i][0] = 0.f; acc[i][1] = 0.f; }

    for (int j = 0; j < HDIM; j++) {
        float2 w = *(const float2*)(W + (size_t)(h*HDIM + j) * E_DIM + e);
        #pragma unroll
        for (int i = 0; i < 8; i++) {
            const float m = Ms[(ig*8 + i)*HDIM + j];
            acc[i][0] += m * w.x;
            acc[i][1] += m * w.y;
        }
    }
    #pragma unroll
    for (int i = 0; i < 8; i++) {
        uint32_t hw, lw;
        split2(acc[i][0], acc[i][1], hw, lw);
        const size_t o = (size_t)(h*HDIM + ig*8 + i) * EW + (e >> 1);
        Wh[o] = hw; Wl[o] = lw;
    }
}

// ============================================================================
// Kernel 3: generic split-pack f32 -> packed bf16 hi/lo.
// ============================================================================
__global__ __launch_bounds__(256) void split_pack_kernel(
    const float* __restrict__ in, uint32_t* __restrict__ hi,
    uint32_t* __restrict__ lo, int nwords)
{
    const int w = blockIdx.x * 256 + threadIdx.x;
    if (w >= nwords) return;
    float2 v = ((const float2*)in)[w];
    uint32_t hw, lw;
    split2(v.x, v.y, hw, lw);
    hi[w] = hw; lo[w] = lw;
}

// ============================================================================
// Kernel 4: bf16x3 GEMM on pre-packed operands. C = A @ W^T + bias.
// A: [M][EW] packed words, W: [1024][EW]. 128x128 tile, 8 warps (64x32 each),
// K-chunk 32 elems (16 words), cp.async double buffer, ldmatrix fragments.
// mode 0: f32 [m][n]; mode 1: packed hi/lo head-major (Q/K);
// mode 2: f32 head-major (V).
// ============================================================================
#define GS 20
#define GB (128*GS)                       // 2560 words per array-buffer

__global__ __launch_bounds__(256) void bf16_gemm_kernel(
    const uint32_t* __restrict__ Ah, const uint32_t* __restrict__ Al,
    const uint32_t* __restrict__ Bh, const uint32_t* __restrict__ Bl,
    const float* __restrict__ bias,
    float* __restrict__ Cf, uint32_t* __restrict__ Ch, uint32_t* __restrict__ Cl,
    int mode)
{
    extern __shared__ uint32_t su[];
    const uint32_t sb = sptr(su);
    const int tid = threadIdx.x;
    const int wid = tid >> 5, lane = tid & 31;
    const int wm = (wid >> 2) * 64, wn = (wid & 3) * 32;
    const int m0 = blockIdx.y * 128, n0 = blockIdx.x * 128;
    const int lr4 = lane >> 2, lc4 = lane & 3;
    const int aR = lane & 15;
    const int aC = (lane & 16) ? 4 : 0;
    const int bR = (lane & 7) + ((lane & 16) ? 8 : 0);
    const int bC = (lane & 8) ? 4 : 0;

    auto load_chunk = [&](int c, int buf) {
        #pragma unroll
        for (int it = 0; it < 2; it++) {
            const int q = tid + it * 256;        // 0..511
            const int row = q >> 2, wc = q & 3;
            const size_t ga = (size_t)(m0 + row) * EW + c*16 + wc*4;
            const size_t gb = (size_t)(n0 + row) * EW + c*16 + wc*4;
            const uint32_t d = (uint32_t)(row*GS + wc*4) * 4;
            cp16(sb + (uint32_t)(0*GB + buf*GB)*4 + d, Ah + ga);
            cp16(sb + (uint32_t)(2*GB + buf*GB)*4 + d, Al + ga);
            cp16(sb + (uint32_t)(4*GB + buf*GB)*4 + d, Bh + gb);
            cp16(sb + (uint32_t)(6*GB + buf*GB)*4 + d, Bl + gb);
        }
    };

    float acc[4][4][4];
    #pragma unroll
    for (int mi = 0; mi < 4; mi++)
        #pragma unroll
        for (int ni = 0; ni < 4; ni++)
            #pragma unroll
            for (int r = 0; r < 4; r++) acc[mi][ni][r] = 0.f;

    load_chunk(0, 0); CP_COMMIT();

    #pragma unroll 1
    for (int c = 0; c < 32; c++) {
        CP_WAIT0();
        __syncthreads();
        if (c < 31) { load_chunk(c + 1, (c + 1) & 1); CP_COMMIT(); }

        const int buf = c & 1;
        const uint32_t bAh = sb + (uint32_t)(buf*GB)*4;
        const uint32_t bAl = sb + (uint32_t)((2+buf)*GB)*4;
        const uint32_t bBh = sb + (uint32_t)((4+buf)*GB)*4;
        const uint32_t bBl = sb + (uint32_t)((6+buf)*GB)*4;

        #pragma unroll
        for (int ks = 0; ks < 2; ks++) {
            uint32_t ah[4][4], al[4][4];
            #pragma unroll
            for (int mi = 0; mi < 4; mi++) {
                const uint32_t off = (uint32_t)((wm + mi*16 + aR)*GS + ks*8 + aC) * 4;
                ldmx4(ah[mi], bAh + off);
                ldmx4(al[mi], bAl + off);
            }
            #pragma unroll
            for (int nb = 0; nb < 2; nb++) {
                uint32_t bh4[4], bl4[4];
                const uint32_t off = (uint32_t)((wn + nb*16 + bR)*GS + ks*8 + bC) * 4;
                ldmx4(bh4, bBh + off);
                ldmx4(bl4, bBl + off);
                #pragma unroll
                for (int h2 = 0; h2 < 2; h2++) {
                    const int ni = nb*2 + h2;
                    #pragma unroll
                    for (int mi = 0; mi < 4; mi++) {
                        mma_bf16(acc[mi][ni], ah[mi], bh4 + h2*2);
                        mma_bf16(acc[mi][ni], al[mi], bh4 + h2*2);
                        mma_bf16(acc[mi][ni], ah[mi], bl4 + h2*2);
                    }
                }
            }
        }
    }

    // ---- epilogue ----
    if (mode == 0) {
        #pragma unroll
        for (int ni = 0; ni < 4; ni++) {
            const int n = n0 + wn + ni*8 + 2*lc4;
            float2 bb = *(const float2*)(bias + n);
            #pragma unroll
            for (int mi = 0; mi < 4; mi++)
                #pragma unroll
                for (int half = 0; half < 2; half++) {
                    const int m = m0 + wm + mi*16 + lr4 + half*8;
                    float2 o;
                    o.x = acc[mi][ni][half*2+0] + bb.x;
                    o.y = acc[mi][ni][half*2+1] + bb.y;
                    *(float2*)(Cf + (size_t)m * E_DIM + n) = o;
                }
        }
    } else if (mode == 1) {
        #pragma unroll
        for (int ni = 0; ni < 4; ni++) {
            const int n = n0 + wn + ni*8 + 2*lc4;
            float2 bb = *(const float2*)(bias + n);
            const int h = n >> 6, dp = (n & 63) >> 1;
            #pragma unroll
            for (int mi = 0; mi < 4; mi++)
                #pragma unroll
                for (int half = 0; half < 2; half++) {
                    const int m = m0 + wm + mi*16 + lr4 + half*8;
                    const int b = m >> 11, s2 = m & 2047;
                    uint32_t hw, lw;
                    split2(acc[mi][ni][half*2+0] + bb.x,
                           acc[mi][ni][half*2+1] + bb.y, hw, lw);
                    const size_t w = ((size_t)(b*HEADS + h) * SEQ + s2) * DW + dp;
                    Ch[w] = hw; Cl[w] = lw;
                }
        }
    } else {
        #pragma unroll
        for (int ni = 0; ni < 4; ni++) {
            const int n = n0 + wn + ni*8 + 2*lc4;
            float2 bb = *(const float2*)(bias + n);
            const int h = n >> 6, dd = n & 63;
            #pragma unroll
            for (int mi = 0; mi < 4; mi++)
                #pragma unroll
                for (int half = 0; half < 2; half++) {
                    const int m = m0 + wm + mi*16 + lr4 + half*8;
                    const int b = m >> 11, s2 = m & 2047;
                    float2 o;
                    o.x = acc[mi][ni][half*2+0] + bb.x;
                    o.y = acc[mi][ni][half*2+1] + bb.y;
                    *(float2*)(Cf + ((size_t)(b*HEADS + h) * SEQ + s2) * HDIM + dd) = o;
                }
        }
    }
}

// ============================================================================
// Kernel 5: transpose+split V: f32 head-major [bh][s][64] -> packed [bh][d][spair]
// ============================================================================
__global__ __launch_bounds__(256) void transpose_split_kernel(
    const float* __restrict__ Vf, uint32_t* __restrict__ Vth,
    uint32_t* __restrict__ Vtl)
{
    __shared__ float ts[64*65];
    const int tid = threadIdx.x;
    const int s0 = blockIdx.x * 64;
    const int bh = blockIdx.y;

    #pragma unroll
    for (int it = 0; it < 4; it++) {
        const int e = tid + it * 256;         // 0..1023 float4 units
        const int s = e >> 4, d4 = (e & 15) * 4;
        float4 v = *(const float4*)(Vf + ((size_t)bh*SEQ + s0 + s) * HDIM + d4);
        ts[s*65 + d4+0] = v.x; ts[s*65 + d4+1] = v.y;
        ts[s*65 + d4+2] = v.z; ts[s*65 + d4+3] = v.w;
    }
    __syncthreads();

    #pragma unroll
    for (int it = 0; it < 8; it++) {
        const int w = tid + it * 256;         // 0..2047 words
        const int d = w >> 5, sp = w & 31;
        uint32_t hw, lw;
        split2(ts[(2*sp)*65 + d], ts[(2*sp+1)*65 + d], hw, lw);
        const size_t o = ((size_t)bh*HDIM + d) * (SEQ/2) + (s0 >> 1) + sp;
        Vth[o] = hw; Vtl[o] = lw;
    }
}

// ============================================================================
// Kernel 6: flash attention on pre-packed bf16 hi/lo. Br=128, Bc=64, 8 warps.
// cp.async double-buffered K/V, ldmatrix fragments, P kept in registers.
// Writes O as packed hi/lo [b*S+s][epair] for the final GEMM.
// ============================================================================
#define FS   36
#define FQH  0
#define FQL  4608
#define FKH  9216
#define FKL  13824
#define FVH  18432
#define FVL  23040
#define FBUF 2304
#define FA_WORDS 27648                      // 110592 bytes

__global__ __launch_bounds__(256) void flash_attn_kernel(
    const uint32_t* __restrict__ Qh, const uint32_t* __restrict__ Ql,
    const uint32_t* __restrict__ Kh, const uint32_t* __restrict__ Kl,
    const uint32_t* __restrict__ Vth, const uint32_t* __restrict__ Vtl,
    uint32_t* __restrict__ Oh, uint32_t* __restrict__ Ol)
{
    extern __shared__ uint32_t su[];
    const uint32_t sb = sptr(su);
    const int tid = threadIdx.x;
    const int wid = tid >> 5, lane = tid & 31;
    const int lr4 = lane >> 2, lc4 = lane & 3;
    const int bh = blockIdx.y;
    const int q0 = blockIdx.x * 128;
    const int aR = lane & 15;
    const int aC = (lane & 16) ? 4 : 0;
    const int bR = (lane & 7) + ((lane & 16) ? 8 : 0);
    const int bC = (lane & 8) ? 4 : 0;

    // Q load (once)
    #pragma unroll
    for (int it = 0; it < 4; it++) {
        const int q = tid + it * 256;           // 0..1023
        const int row = q >> 3, wc = q & 7;
        const size_t g = ((size_t)bh*SEQ + q0 + row) * DW + wc*4;
        const uint32_t d = (uint32_t)(row*FS + wc*4) * 4;
        cp16(sb + FQH*4 + d, Qh + g);
        cp16(sb + FQL*4 + d, Ql + g);
    }

    auto load_tile = [&](int kt, int buf) {
        const int n0 = kt * 64;
        #pragma unroll
        for (int it = 0; it < 2; it++) {
            const int q = tid + it * 256;       // 0..511
            const int row = q >> 3, wc = q & 7;
            const uint32_t d = (uint32_t)(row*FS + wc*4) * 4;
            const size_t gk = ((size_t)bh*SEQ + n0 + row) * DW + wc*4;
            cp16(sb + (uint32_t)(FKH + buf*FBUF)*4 + d, Kh + gk);
            cp16(sb + (uint32_t)(FKL + buf*FBUF)*4 + d, Kl + gk);
            const size_t gv = ((size_t)bh*HDIM + row) * (SEQ/2) + (n0 >> 1) + wc*4;
            cp16(sb + (uint32_t)(FVH + buf*FBUF)*4 + d, Vth + gv);
            cp16(sb + (uint32_t)(FVL + buf*FBUF)*4 + d, Vtl + gv);
        }
    };

    load_tile(0, 0);
    CP_COMMIT();

    float m0 = -1e30f, m1 = -1e30f, l0r = 0.f, l1r = 0.f;
    float o[8][4];
    #pragma unroll
    for (int ni = 0; ni < 8; ni++)
        #pragma unroll
        for (int r = 0; r < 4; r++) o[ni][r] = 0.f;

    #pragma unroll 1
    for (int kt = 0; kt < SEQ/64; kt++) {
        CP_WAIT0();
        __syncthreads();
        if (kt + 1 < SEQ/64) { load_tile(kt + 1, (kt + 1) & 1); CP_COMMIT(); }
        const int buf = kt & 1;
        const uint32_t bKh = sb + (uint32_t)(FKH + buf*FBUF)*4;
        const uint32_t bKl = sb + (uint32_t)(FKL + buf*FBUF)*4;
        const uint32_t bVh = sb + (uint32_t)(FVH + buf*FBUF)*4;
        const uint32_t bVl = sb + (uint32_t)(FVL + buf*FBUF)*4;

        // S = Q @ K^T  (bf16x3, raw scale)
        float s[8][4];
        #pragma unroll
        for (int ni = 0; ni < 8; ni++)
            #pragma unroll
            for (int r = 0; r < 4; r++) s[ni][r] = 0.f;

        #pragma unroll
        for (int ks = 0; ks < 4; ks++) {
            uint32_t ah[4], al[4];
            const uint32_t aoff = (uint32_t)((wid*16 + aR)*FS + ks*8 + aC) * 4;
            ldmx4(ah, sb + FQH*4 + aoff);
            ldmx4(al, sb + FQL*4 + aoff);
            #pragma unroll
            for (int nb = 0; nb < 4; nb++) {
                uint32_t kh4[4], kl4[4];
                const uint32_t boff = (uint32_t)((nb*16 + bR)*FS + ks*8 + bC) * 4;
                ldmx4(kh4, bKh + boff);
                ldmx4(kl4, bKl + boff);
                #pragma unroll
                for (int h2 = 0; h2 < 2; h2++) {
                    const int ni = nb*2 + h2;
                    mma_bf16(s[ni], ah, kh4 + h2*2);
                    mma_bf16(s[ni], al, kh4 + h2*2);
                    mma_bf16(s[ni], ah, kl4 + h2*2);
                }
            }
        }

        // online softmax (1/8 scale folded in here)
        float v0 = -1e30f, v1 = -1e30f;
        #pragma unroll
        for (int ni = 0; ni < 8; ni++) {
            v0 = fmaxf(v0, fmaxf(s[ni][0], s[ni][1]));
            v1 = fmaxf(v1, fmaxf(s[ni][2], s[ni][3]));
        }
        v0 = fmaxf(v0, __shfl_xor_sync(0xffffffffu, v0, 1));
        v0 = fmaxf(v0, __shfl_xor_sync(0xffffffffu, v0, 2));
        v1 = fmaxf(v1, __shfl_xor_sync(0xffffffffu, v1, 1));
        v1 = fmaxf(v1, __shfl_xor_sync(0xffffffffu, v1, 2));
        const float mn0 = fmaxf(m0, 0.125f * v0), mn1 = fmaxf(m1, 0.125f * v1);
        const float al0 = __expf(m0 - mn0), al1 = __expf(m1 - mn1);
        m0 = mn0; m1 = mn1;

        float rs0 = 0.f, rs1 = 0.f;
        #pragma unroll
        for (int ni = 0; ni < 8; ni++) {
            s[ni][0] = __expf(fmaf(s[ni][0], 0.125f, -mn0));
            s[ni][1] = __expf(fmaf(s[ni][1], 0.125f, -mn0));
            s[ni][2] = __expf(fmaf(s[ni][2], 0.125f, -mn1));
            s[ni][3] = __expf(fmaf(s[ni][3], 0.125f, -mn1));
            rs0 += s[ni][0] + s[ni][1];
            rs1 += s[ni][2] + s[ni][3];
        }
        rs0 += __shfl_xor_sync(0xffffffffu, rs0, 1);
        rs0 += __shfl_xor_sync(0xffffffffu, rs0, 2);
        rs1 += __shfl_xor_sync(0xffffffffu, rs1, 1);
        rs1 += __shfl_xor_sync(0xffffffffu, rs1, 2);
        l0r = l0r * al0 + rs0;
        l1r = l1r * al1 + rs1;
        #pragma unroll
        for (int ni = 0; ni < 8; ni++) {
            o[ni][0] *= al0; o[ni][1] *= al0;
            o[ni][2] *= al1; o[ni][3] *= al1;
        }

        // O += P @ V  (P fragments directly from registers)
        #pragma unroll
        for (int b = 0; b < 4; b++) {
            uint32_t ph[4], pl[4];
            split2(s[2*b][0],   s[2*b][1],   ph[0], pl[0]);
            split2(s[2*b][2],   s[2*b][3],   ph[1], pl[1]);
            split2(s[2*b+1][0], s[2*b+1][1], ph[2], pl[2]);
            split2(s[2*b+1][2], s[2*b+1][3], ph[3], pl[3]);
            #pragma unroll
            for (int nb = 0; nb < 4; nb++) {
                uint32_t vh4[4], vl4[4];
                const uint32_t voff = (uint32_t)((nb*16 + bR)*FS + b*8 + bC) * 4;
                ldmx4(vh4, bVh + voff);
                ldmx4(vl4, bVl + voff);
                #pragma unroll
                for (int h2 = 0; h2 < 2; h2++) {
                    const int ni = nb*2 + h2;
                    mma_bf16(o[ni], ph, vh4 + h2*2);
                    mma_bf16(o[ni], pl, vh4 + h2*2);
                    mma_bf16(o[ni], ph, vl4 + h2*2);
                }
            }
        }
    }

    // epilogue: normalize, split-pack, write [b*S+s][epair]
    const int b = bh >> 4, h = bh & 15;
    const float inv0 = 1.f / l0r, inv1 = 1.f / l1r;
    const int rA = wid*16 + lr4;
    #pragma unroll
    for (int ni = 0; ni < 8; ni++) {
        const int ep = (h*HDIM + ni*8 + 2*lc4) >> 1;
        uint32_t hw, lw;
        split2(o[ni][0]*inv0, o[ni][1]*inv0, hw, lw);
        size_t w = ((size_t)b*SEQ + q0 + rA) * EW + ep;
        Oh[w] = hw; Ol[w] = lw;
        split2(o[ni][2]*inv1, o[ni][3]*inv1, hw, lw);
        w = ((size_t)b*SEQ + q0 + rA + 8) * EW + ep;
        Oh[w] = hw; Ol[w] = lw;
    }
}

// ============================================================================
// Host launcher
// ============================================================================
extern "C" void kernel_launch(void* const* d_in, const int* in_sizes, int n_in,
                              void* d_out, int out_size)
{
    (void)in_sizes; (void)n_in; (void)out_size;

    const float* query   = (const float*)d_in[0];
    const float* key     = (const float*)d_in[1];
    const float* value   = (const float*)d_in[2];
    const float* wq      = (const float*)d_in[3];
    const float* bq      = (const float*)d_in[4];
    const float* wk      = (const float*)d_in[5];
    const float* bk      = (const float*)d_in[6];
    const float* wv      = (const float*)d_in[7];
    const float* bv      = (const float*)d_in[8];
    const float* wo      = (const float*)d_in[9];
    const float* bo      = (const float*)d_in[10];
    const float* q_theta = (const float*)d_in[11];
    const float* q_phi   = (const float*)d_in[12];
    const float* q_preW  = (const float*)d_in[13];
    const float* q_preb  = (const float*)d_in[14];
    const float* q_postW = (const float*)d_in[15];
    const float* q_postb = (const float*)d_in[16];
    const float* k_theta = (const float*)d_in[17];
    const float* k_phi   = (const float*)d_in[18];
    const float* k_preW  = (const float*)d_in[19];
    const float* k_preb  = (const float*)d_in[20];
    const float* k_postW = (const float*)d_in[21];
    const float* k_postb = (const float*)d_in[22];
    float* out = (float*)d_out;

    float *pMq, *pMk, *pbq, *pbk, *pVf;
    uint32_t *pWqh, *pWql, *pWkh, *pWkl, *pWvh, *pWvl, *pWoh, *pWol;
    uint32_t *pXqh, *pXql, *pXkh, *pXkl, *pXvh, *pXvl;
    uint32_t *pQh, *pQl, *pKh, *pKl, *pVth, *pVtl, *pOh, *pOl;
    cudaGetSymbolAddress((void**)&pMq, g_Mq);
    cudaGetSymbolAddress((void**)&pMk, g_Mk);
    cudaGetSymbolAddress((void**)&pbq, g_bq);
    cudaGetSymbolAddress((void**)&pbk, g_bk);
    cudaGetSymbolAddress((void**)&pWqh, g_Wqh);
    cudaGetSymbolAddress((void**)&pWql, g_Wql);
    cudaGetSymbolAddress((void**)&pWkh, g_Wkh);
    cudaGetSymbolAddress((void**)&pWkl, g_Wkl);
    cudaGetSymbolAddress((void**)&pWvh, g_Wvh);
    cudaGetSymbolAddress((void**)&pWvl, g_Wvl);
    cudaGetSymbolAddress((void**)&pWoh, g_Woh);
    cudaGetSymbolAddress((void**)&pWol, g_Wol);
    cudaGetSymbolAddress((void**)&pXqh, g_Xqh);
    cudaGetSymbolAddress((void**)&pXql, g_Xql);
    cudaGetSymbolAddress((void**)&pXkh, g_Xkh);
    cudaGetSymbolAddress((void**)&pXkl, g_Xkl);
    cudaGetSymbolAddress((void**)&pXvh, g_Xvh);
    cudaGetSymbolAddress((void**)&pXvl, g_Xvl);
    cudaGetSymbolAddress((void**)&pQh, g_Qh);
    cudaGetSymbolAddress((void**)&pQl, g_Ql);
    cudaGetSymbolAddress((void**)&pKh, g_Kh);
    cudaGetSymbolAddress((void**)&pKl, g_Kl);
    cudaGetSymbolAddress((void**)&pVf, g_Vf);
    cudaGetSymbolAddress((void**)&pVth, g_Vth);
    cudaGetSymbolAddress((void**)&pVtl, g_Vtl);
    cudaGetSymbolAddress((void**)&pOh, g_Oh);
    cudaGetSymbolAddress((void**)&pOl, g_Ol);

    // 1) effective quantum operators (fp32)
    build_eff_kernel<<<1, 64>>>(q_theta, q_phi, q_preW, q_preb, q_postW, q_postb,
                                bq, pMq, pbq);
    build_eff_kernel<<<1, 64>>>(k_theta, k_phi, k_preW, k_preb, k_postW, k_postb,
                                bk, pMk, pbk);

    // 2) fold+split weights; split wv/wo; split inputs
    fold_split_kernel<<<dim3(HEADS, 16), 256>>>(wq, pMq, pWqh, pWql);
    fold_split_kernel<<<dim3(HEADS, 16), 256>>>(wk, pMk, pWkh, pWkl);
    split_pack_kernel<<<(E_DIM*EW)/256, 256>>>(wv, pWvh, pWvl, E_DIM*EW);
    split_pack_kernel<<<(E_DIM*EW)/256, 256>>>(wo, pWoh, pWol, E_DIM*EW);
    split_pack_kernel<<<(ROWS*EW)/256, 256>>>(query, pXqh, pXql, ROWS*EW);
    split_pack_kernel<<<(ROWS*EW)/256, 256>>>(key,   pXkh, pXkl, ROWS*EW);
    split_pack_kernel<<<(ROWS*EW)/256, 256>>>(value, pXvh, pXvl, ROWS*EW);

    // 3) projections
    const int gemm_smem = 8 * GB * (int)sizeof(uint32_t);   // 81920
    cudaFuncSetAttribute(bf16_gemm_kernel,
                         cudaFuncAttributeMaxDynamicSharedMemorySize, gemm_smem);
    dim3 ggrid(E_DIM/128, ROWS/128);
    bf16_gemm_kernel<<<ggrid, 256, gemm_smem>>>(pXqh, pXql, pWqh, pWql, pbq,
                                                nullptr, pQh, pQl, 1);
    bf16_gemm_kernel<<<ggrid, 256, gemm_smem>>>(pXkh, pXkl, pWkh, pWkl, pbk,
                                                nullptr, pKh, pKl, 1);
    bf16_gemm_kernel<<<ggrid, 256, gemm_smem>>>(pXvh, pXvl, pWvh, pWvl, bv,
                                                pVf, nullptr, nullptr, 2);

    // 4) V transpose+split
    transpose_split_kernel<<<dim3(SEQ/64, BATCH*HEADS), 256>>>(pVf, pVth, pVtl);

    // 5) flash attention
    const int fa_smem = FA_WORDS * (int)sizeof(uint32_t);   // 110592
    cudaFuncSetAttribute(flash_attn_kernel,
                         cudaFuncAttributeMaxDynamicSharedMemorySize, fa_smem);
    flash_attn_kernel<<<dim3(SEQ/128, BATCH*HEADS), 256, fa_smem>>>(
        pQh, pQl, pKh, pKl, pVth, pVtl, pOh, pOl);

    // 6) output projection
    bf16_gemm_kernel<<<ggrid, 256, gemm_smem>>>(pOh, pOl, pWoh, pWol, bo,
                                                out, nullptr, nullptr, 0);
}